// round 12
// baseline (speedup 1.0000x reference)
#include <cuda_runtime.h>
#include <cuda_fp16.h>
#include <cstdint>

static constexpr int BB  = 4;
static constexpr int SS  = 2048;
static constexpr int DD  = 1024;
static constexpr int HH  = 16;
static constexpr int HSZ = 64;

// Scratch. Everything fp16 (same 11-bit mantissa grid as tf32; fp32 accum).
// q/k/v: [b*h][row][64] fp16 = 128 B rows. q pre-scaled by 0.125*log2(e).
__device__ uint16_t g_qs[BB * HH * SS * 64];
__device__ uint16_t g_ks[BB * HH * SS * 64];
__device__ uint16_t g_vs[BB * HH * SS * 64];
__device__ uint16_t g_ath[BB * SS * DD];     // attention out, fp16
__device__ uint16_t g_xh[BB * SS * DD];      // x, fp16
__device__ uint16_t g_wh[4 * DD * DD];       // Wq|Wk|Wv|Wo, fp16

// ---------------------------------------------------------------------------
// Helpers (sm_80-era PTX only: valid on plain compute_103)
// ---------------------------------------------------------------------------
__device__ __forceinline__ uint32_t smem_u32(const void* p) {
    uint32_t a;
    asm("{ .reg .u64 t; cvta.to.shared.u64 t, %1; cvt.u32.u64 %0, t; }"
        : "=r"(a) : "l"(p));
    return a;
}
__device__ __forceinline__ void cp16(uint32_t dst, const void* src) {
    asm volatile("cp.async.cg.shared.global [%0], [%1], 16;"
                 :: "r"(dst), "l"(src));
}
__device__ __forceinline__ void cp_commit() {
    asm volatile("cp.async.commit_group;" ::: "memory");
}
template <int N>
__device__ __forceinline__ void cp_wait() {
    asm volatile("cp.async.wait_group %0;" :: "n"(N) : "memory");
}
__device__ __forceinline__ void mma16h(float* c, const uint32_t* a,
                                       uint32_t b0, uint32_t b1) {
    asm volatile(
        "mma.sync.aligned.m16n8k16.row.col.f32.f16.f16.f32 "
        "{%0,%1,%2,%3}, {%4,%5,%6,%7}, {%8,%9}, {%0,%1,%2,%3};"
        : "+f"(c[0]), "+f"(c[1]), "+f"(c[2]), "+f"(c[3])
        : "r"(a[0]), "r"(a[1]), "r"(a[2]), "r"(a[3]), "r"(b0), "r"(b1));
}
__device__ __forceinline__ void ldm4(uint32_t* r, uint32_t a) {
    asm volatile("ldmatrix.sync.aligned.m8n8.x4.shared.b16 {%0,%1,%2,%3}, [%4];"
                 : "=r"(r[0]), "=r"(r[1]), "=r"(r[2]), "=r"(r[3]) : "r"(a));
}
__device__ __forceinline__ void ldm4t(uint32_t* r, uint32_t a) {
    asm volatile("ldmatrix.sync.aligned.m8n8.x4.trans.shared.b16 {%0,%1,%2,%3}, [%4];"
                 : "=r"(r[0]), "=r"(r[1]), "=r"(r[2]), "=r"(r[3]) : "r"(a));
}
__device__ __forceinline__ uint32_t h2pack(float v0, float v1) {
    __half2 h = __floats2half2_rn(v0, v1);
    return *reinterpret_cast<uint32_t*>(&h);
}

// ---------------------------------------------------------------------------
// Conversion: x and the four W matrices -> fp16 copies (one float4/thread).
// ---------------------------------------------------------------------------
__global__ __launch_bounds__(256)
void round_conv(const float* __restrict__ x,  const float* __restrict__ Wq,
                const float* __restrict__ Wk, const float* __restrict__ Wv,
                const float* __restrict__ Wo)
{
    const int idx = blockIdx.x * 256 + threadIdx.x;
    const float4* src;
    uint32_t* dst;
    if (idx < 2097152) {                       // x: 8,388,608 floats
        src = (const float4*)x + idx;
        dst = (uint32_t*)g_xh + idx * 2;
    } else {
        const int wi  = idx - 2097152;
        const int z   = wi >> 18;              // 262,144 float4 per W
        const int off = wi & 262143;
        const float* w = (z == 0) ? Wq : (z == 1) ? Wk : (z == 2) ? Wv : Wo;
        src = (const float4*)w + off;
        dst = (uint32_t*)g_wh + ((size_t)z * 262144 + off) * 2;
    }
    const float4 v = *src;
    dst[0] = h2pack(v.x, v.y);
    dst[1] = h2pack(v.z, v.w);
}

// ---------------------------------------------------------------------------
// fp16 mma.sync GEMM (fp32 accumulate), ldmatrix feed, single-sync mainloop.
// CTA 128x128, K-chunk 64 (128 B fp16 rows), 3-stage cp.async, 256 threads.
// MODE 0: A=g_ath, W=g_wh[3], +bias, writes Cout fp32.
// MODE 1: A=g_xh, z selects g_wh[z]; epilogue writes fp16 g_qs/ks/vs.
// ---------------------------------------------------------------------------
static constexpr int GSTAGES   = 3;
static constexpr int NCHUNK    = 16;                  // 1024 / 64
static constexpr int STAGE_B   = 2 * 128 * 128;       // A 16KB + B 16KB
static constexpr int GEMM_SMEM = GSTAGES * STAGE_B;   // 98304 B

template <int MODE>
__global__ __launch_bounds__(256, 2)
void gemm_tc(const float* __restrict__ bias, float* __restrict__ Cout)
{
    extern __shared__ char smch[];
    const uint32_t sbase = smem_u32(smch);

    const int tid  = threadIdx.x;
    const int wid  = tid >> 5;
    const int lane = tid & 31;
    const int gID  = lane >> 2;
    const int ctg  = lane & 3;
    const int wRow = (wid & 1) * 64;
    const int wCol = (wid >> 1) * 32;

    const int brow = blockIdx.x;
    const int bcol = blockIdx.y;
    const int z    = (MODE == 0) ? 3 : blockIdx.z;

    const uint16_t* Ain = (MODE == 0) ? g_ath : g_xh;
    const char* ap = (const char*)(Ain + (size_t)(brow * 128) * DD);
    const char* wp = (const char*)(g_wh + (size_t)z * (DD * DD)
                                        + (size_t)(bcol * 128) * DD);

    // ldmatrix lane constants
    const int rA = lane & 15;          // A row-in-16
    const int sB = lane >> 4;          // granule-half selector (A) / row-group (B)
    const int rB = lane & 7;           // B row-within-8
    const int hB = (lane >> 3) & 1;    // B granule-half selector

    auto load_chunk = [&](int chunk, int stage) {
        const uint32_t aB = sbase + (uint32_t)(stage * STAGE_B);
        const uint32_t bB = aB + 16384u;
        const char* a0 = ap + chunk * 128;          // 64 fp16 cols = 128 B
        const char* w0 = wp + chunk * 128;
#pragma unroll
        for (int u = 0; u < 4; u++) {
            const int gi  = tid + 256 * u;          // 0..1023
            const int row = gi >> 3;
            const int ch  = gi & 7;
            const uint32_t off =
                (uint32_t)(row * 128 + ((ch ^ (row & 7)) << 4));
            cp16(aB + off, a0 + (size_t)row * 2048 + ch * 16);
            cp16(bB + off, w0 + (size_t)row * 2048 + ch * 16);
        }
        cp_commit();
    };

    float c[4][4][4];
#pragma unroll
    for (int i = 0; i < 4; i++)
#pragma unroll
        for (int j = 0; j < 4; j++)
#pragma unroll
            for (int r = 0; r < 4; r++) c[i][j][r] = 0.f;

    load_chunk(0, 0);
    load_chunk(1, 1);

    int stage = 0;
    for (int i = 0; i < NCHUNK; i++) {
        // wait for chunk i (pending: {i, i+1} or just {i} at the tail)
        if (i + 1 < NCHUNK) cp_wait<1>(); else cp_wait<0>();
        __syncthreads();   // chunk i visible to all; stage (i+2)%3 free
        if (i + 2 < NCHUNK) load_chunk(i + 2, (stage + 2) % GSTAGES);

        const uint32_t sA = sbase + (uint32_t)(stage * STAGE_B);
        const uint32_t sBa = sA + 16384u;
        uint32_t aBase[4], bBase[2];
#pragma unroll
        for (int mt = 0; mt < 4; mt++)
            aBase[mt] = sA + (uint32_t)((wRow + mt * 16 + rA) * 128);
#pragma unroll
        for (int ntp = 0; ntp < 2; ntp++)
            bBase[ntp] = sBa + (uint32_t)((wCol + ntp * 16 + sB * 8 + rB) * 128);

#pragma unroll
        for (int kb = 0; kb < 4; kb++) {            // 4 k16 blocks per chunk
            uint32_t a[4][4], b[2][4];
            const uint32_t offA = (uint32_t)(((2 * kb + sB) ^ (rA & 7)) << 4);
            const uint32_t offB = (uint32_t)(((2 * kb + hB) ^ rB) << 4);
#pragma unroll
            for (int mt = 0; mt < 4; mt++) ldm4(a[mt], aBase[mt] + offA);
#pragma unroll
            for (int ntp = 0; ntp < 2; ntp++) ldm4(b[ntp], bBase[ntp] + offB);
#pragma unroll
            for (int mt = 0; mt < 4; mt++)
#pragma unroll
                for (int ntp = 0; ntp < 2; ntp++) {
                    mma16h(c[mt][2 * ntp],     a[mt], b[ntp][0], b[ntp][1]);
                    mma16h(c[mt][2 * ntp + 1], a[mt], b[ntp][2], b[ntp][3]);
                }
        }
        stage = (stage + 1) % GSTAGES;
    }

#pragma unroll
    for (int mt = 0; mt < 4; mt++) {
#pragma unroll
        for (int half = 0; half < 2; half++) {
            const int m = brow * 128 + wRow + mt * 16 + gID + half * 8;
            if (MODE == 0) {
                float* rowp = &Cout[(size_t)m * DD + bcol * 128];
#pragma unroll
                for (int nt = 0; nt < 4; nt++) {
                    const int n = wCol + nt * 8 + ctg * 2;
                    float2 v;
                    v.x = c[mt][nt][half * 2 + 0] + bias[bcol * 128 + n];
                    v.y = c[mt][nt][half * 2 + 1] + bias[bcol * 128 + n + 1];
                    *reinterpret_cast<float2*>(&rowp[n]) = v;
                }
            } else {
                const int bb = m >> 11;
                const int s  = m & 2047;
                uint16_t* dst = (z == 0) ? g_qs : (z == 1) ? g_ks : g_vs;
                // q pre-scale folds 1/sqrt(64) AND log2(e) for exp2 softmax
                const float qs = (z == 0) ? 0.125f * 1.44269504088896f : 1.0f;
#pragma unroll
                for (int nt = 0; nt < 4; nt++) {
                    const int n  = bcol * 128 + wCol + nt * 8 + ctg * 2;
                    const int h  = n >> 6;
                    const int hs = n & 63;
                    const uint32_t hv = h2pack(c[mt][nt][half * 2 + 0] * qs,
                                               c[mt][nt][half * 2 + 1] * qs);
                    *(uint32_t*)&dst[((size_t)(bb * HH + h) * SS + s) * 64 + hs] = hv;
                }
            }
        }
    }
}

// ---------------------------------------------------------------------------
// Causal flash attention, single-pass fp16, exp2-domain softmax.
// 128 queries/CTA, 64-key tiles, 3-stage cp.async, single sync per tile.
// smem: KV[3][16KB] | Qstage[8][2KB] = 64 KB.
// ---------------------------------------------------------------------------
static constexpr int ATTN_SMEM = 65536;

__global__ __launch_bounds__(256)
void attn_tc()
{
    extern __shared__ char smem[];
    const uint32_t sbase = smem_u32(smem);

    const int tid  = threadIdx.x;
    const int w    = tid >> 5;
    const int lane = tid & 31;
    const int gID  = lane >> 2;
    const int ctg  = lane & 3;

    const int qt = (int)gridDim.x - 1 - (int)blockIdx.x;  // heavy tiles first
    const int bh = blockIdx.y;
    const int q0 = qt * 128;
    const int NT = 2 * qt + 2;

    const char* kgB = (const char*)g_ks + (size_t)bh * SS * 128;
    const char* vgB = (const char*)g_vs + (size_t)bh * SS * 128;
    const char* qgB = (const char*)g_qs + (size_t)(bh * SS + q0 + w * 16) * 128;

    const uint32_t PsB = sbase + 49152u + (uint32_t)w * 2048u;

    const int rB = lane & 7;
    const int hB = (lane >> 3) & 1;
    const int sB = lane >> 4;
    const int rA = lane & 15;

    auto loadKV = [&](int t, int st) {
        const uint32_t kb = sbase + (uint32_t)st * 16384u;
        const uint32_t vb = kb + 8192u;
        const char* kp = kgB + (size_t)t * 64 * 128;
        const char* vp = vgB + (size_t)t * 64 * 128;
#pragma unroll
        for (int u = 0; u < 2; u++) {
            const int gi = tid + 256 * u;
            const int row = gi >> 3, ch = gi & 7;
            const uint32_t off = (uint32_t)(row * 128 + ((ch ^ (row & 7)) << 4));
            cp16(kb + off, kp + row * 128 + ch * 16);
            cp16(vb + off, vp + row * 128 + ch * 16);
        }
        cp_commit();
    };

    loadKV(0, 0);
    // stage Q through this warp's private region (read once into registers)
#pragma unroll
    for (int u = 0; u < 4; u++) {
        const int idx = lane + 32 * u;
        const int row = idx >> 3, ch = idx & 7;
        const uint32_t off = (uint32_t)(row * 128 + ((ch ^ (row & 7)) << 4));
        cp16(PsB + off, qgB + row * 128 + ch * 16);
    }
    cp_commit();
    cp_wait<0>();       // Q + KV tile 0 complete (own thread)
    __syncwarp();

    uint32_t qf[4][4];
#pragma unroll
    for (int j = 0; j < 4; j++)
        ldm4(qf[j], PsB + (uint32_t)(rA * 128 + (((2 * j + sB) ^ (rA & 7)) << 4)));
    __syncthreads();    // KV tile 0 visible to all warps

    if (1 < NT) loadKV(1, 1);   // prefetch tile 1 (always true: NT >= 2)

    float o[8][4];
#pragma unroll
    for (int nt = 0; nt < 8; nt++)
#pragma unroll
        for (int i = 0; i < 4; i++) o[nt][i] = 0.f;
    float m_[2] = {-1e30f, -1e30f};
    float l_[2] = {0.f, 0.f};

    for (int t = 0; t < NT; t++) {
        if (t > 0) {
            // pending: {t, t+1} (t+1 issued last iter) or {t} at tail
            if (t + 1 < NT) cp_wait<1>(); else cp_wait<0>();
            __syncthreads();    // tile t visible; stage (t+2)%3 free
        }
        if (t + 2 < NT) loadKV(t + 2, (t + 2) % 3);

        if (t * 64 <= q0 + w * 16 + 15) {
            const uint32_t kst = sbase + (uint32_t)(t % 3) * 16384u;
            const uint32_t vst = kst + 8192u;

            int ntpLim = 4;
            if (t >= 2 * qt)
                ntpLim = min(4, (q0 + 16 * w + 15 - t * 64) / 16 + 1);

            float s[8][4];
#pragma unroll
            for (int nt = 0; nt < 8; nt++)
#pragma unroll
                for (int i = 0; i < 4; i++) s[nt][i] = 0.f;

#pragma unroll
            for (int ntp = 0; ntp < 4; ntp++) {
                if (ntp >= ntpLim) continue;
                const uint32_t ntb = kst + (uint32_t)((2 * ntp + sB) * 1024 + rB * 128);
#pragma unroll
                for (int j = 0; j < 4; j++) {
                    uint32_t kf[4];
                    ldm4(kf, ntb + (uint32_t)(((2 * j + hB) ^ rB) << 4));
                    mma16h(s[2 * ntp],     qf[j], kf[0], kf[1]);
                    mma16h(s[2 * ntp + 1], qf[j], kf[2], kf[3]);
                }
            }

            if (t >= 2 * qt) {
#pragma unroll
                for (int nt = 0; nt < 8; nt++)
#pragma unroll
                    for (int i = 0; i < 4; i++) {
                        const int kg = t * 64 + nt * 8 + 2 * ctg + (i & 1);
                        const int qg = q0 + w * 16 + gID + (i >> 1) * 8;
                        if (kg > qg) s[nt][i] = -1e30f;
                    }
            }

            // online softmax in log2 domain (q carries the log2e factor)
#pragma unroll
            for (int h2 = 0; h2 < 2; h2++) {
                float rm = -1e30f;
#pragma unroll
                for (int nt = 0; nt < 8; nt++)
                    rm = fmaxf(rm, fmaxf(s[nt][2 * h2], s[nt][2 * h2 + 1]));
                rm = fmaxf(rm, __shfl_xor_sync(0xffffffffu, rm, 1));
                rm = fmaxf(rm, __shfl_xor_sync(0xffffffffu, rm, 2));
                const float mn    = fmaxf(m_[h2], rm);
                const float alpha = exp2f(m_[h2] - mn);
                m_[h2] = mn;
                float rs = 0.f;
#pragma unroll
                for (int nt = 0; nt < 8; nt++) {
                    const float p0 = exp2f(s[nt][2 * h2]     - mn);
                    const float p1 = exp2f(s[nt][2 * h2 + 1] - mn);
                    s[nt][2 * h2]     = p0;
                    s[nt][2 * h2 + 1] = p1;
                    rs += p0 + p1;
                }
                rs += __shfl_xor_sync(0xffffffffu, rs, 1);
                rs += __shfl_xor_sync(0xffffffffu, rs, 2);
                l_[h2] = l_[h2] * alpha + rs;
#pragma unroll
                for (int nt = 0; nt < 8; nt++) {
                    o[nt][2 * h2]     *= alpha;
                    o[nt][2 * h2 + 1] *= alpha;
                }
            }

            // O += P V (fp16 P packed from registers; V ldmatrix.trans)
#pragma unroll
            for (int j = 0; j < 4; j++) {
                if (j >= ntpLim) continue;
                uint32_t pf[4];
                pf[0] = h2pack(s[2*j][0],   s[2*j][1]);
                pf[1] = h2pack(s[2*j][2],   s[2*j][3]);
                pf[2] = h2pack(s[2*j+1][0], s[2*j+1][1]);
                pf[3] = h2pack(s[2*j+1][2], s[2*j+1][3]);
                const uint32_t jrow = vst + (uint32_t)((2 * j + hB) * 1024 + rB * 128);
#pragma unroll
                for (int ntp = 0; ntp < 4; ntp++) {
                    uint32_t vf[4];
                    ldm4t(vf, jrow + (uint32_t)(((2 * ntp + sB) ^ rB) << 4));
                    mma16h(o[2 * ntp],     pf, vf[0], vf[1]);
                    mma16h(o[2 * ntp + 1], pf, vf[2], vf[3]);
                }
            }
        }
    }

    // normalize, write fp16 [b, s, h*64+d] for the fp16 output GEMM
    const int hh = bh & 15;
    const int bb = bh >> 4;
    const float i0 = 1.f / l_[0];
    const float i1 = 1.f / l_[1];
    const int qg0 = q0 + w * 16 + gID;
#pragma unroll
    for (int nt = 0; nt < 8; nt++) {
        const int d0 = hh * 64 + nt * 8 + 2 * ctg;
        *(uint32_t*)&g_ath[(size_t)(bb * SS + qg0) * DD + d0] =
            h2pack(o[nt][0] * i0, o[nt][1] * i0);
        *(uint32_t*)&g_ath[(size_t)(bb * SS + qg0 + 8) * DD + d0] =
            h2pack(o[nt][2] * i1, o[nt][3] * i1);
    }
}

// ---------------------------------------------------------------------------

extern "C" void kernel_launch(void* const* d_in, const int* in_sizes, int n_in,
                              void* d_out, int out_size)
{
    const float* x  = (const float*)d_in[0];
    const float* Wk = (const float*)d_in[1];
    const float* Wq = (const float*)d_in[2];
    const float* Wv = (const float*)d_in[3];
    const float* Wo = (const float*)d_in[4];
    const float* bo = (const float*)d_in[5];
    float* out = (float*)d_out;

    cudaFuncSetAttribute(attn_tc,
                         cudaFuncAttributeMaxDynamicSharedMemorySize, ATTN_SMEM);
    cudaFuncSetAttribute(gemm_tc<0>,
                         cudaFuncAttributeMaxDynamicSharedMemorySize, GEMM_SMEM);
    cudaFuncSetAttribute(gemm_tc<1>,
                         cudaFuncAttributeMaxDynamicSharedMemorySize, GEMM_SMEM);

    // 0) fp16-convert x and weights (g_wh order: Wq, Wk, Wv, Wo)
    round_conv<<<12288, 256>>>(x, Wq, Wk, Wv, Wo);

    // 1) QKV projections (fp16 MMA, fp32 accum) -> fp16 q/k/v
    gemm_tc<1><<<dim3(BB * SS / 128, DD / 128, 3), 256, GEMM_SMEM>>>(
        nullptr, nullptr);

    // 2) Tensor-core causal flash attention (fp16, exp2 softmax) -> g_ath
    attn_tc<<<dim3(SS / 128, BB * HH), 256, ATTN_SMEM>>>();

    // 3) Output projection (fp16 MMA): out = g_ath @ Wo^T + bo
    gemm_tc<0><<<dim3(BB * SS / 128, DD / 128, 1), 256, GEMM_SMEM>>>(bo, out);
}

// round 13
// speedup vs baseline: 1.0262x; 1.0262x over previous
#include <cuda_runtime.h>
#include <cuda_fp16.h>
#include <cstdint>

static constexpr int BB  = 4;
static constexpr int SS  = 2048;
static constexpr int DD  = 1024;
static constexpr int HH  = 16;
static constexpr int HSZ = 64;

// Scratch. Everything fp16 (same 11-bit mantissa grid as tf32; fp32 accum).
// q/k/v: [b*h][row][64] fp16 = 128 B rows. q pre-scaled by 0.125*log2(e).
__device__ uint16_t g_qs[BB * HH * SS * 64];
__device__ uint16_t g_ks[BB * HH * SS * 64];
__device__ uint16_t g_vs[BB * HH * SS * 64];
__device__ uint16_t g_ath[BB * SS * DD];     // attention out, fp16
__device__ uint16_t g_xh[BB * SS * DD];      // x, fp16
__device__ uint16_t g_wh[4 * DD * DD];       // Wq|Wk|Wv|Wo, fp16

// ---------------------------------------------------------------------------
// Helpers (sm_80-era PTX only: valid on plain compute_103)
// ---------------------------------------------------------------------------
__device__ __forceinline__ uint32_t smem_u32(const void* p) {
    uint32_t a;
    asm("{ .reg .u64 t; cvta.to.shared.u64 t, %1; cvt.u32.u64 %0, t; }"
        : "=r"(a) : "l"(p));
    return a;
}
__device__ __forceinline__ void cp16(uint32_t dst, const void* src) {
    asm volatile("cp.async.cg.shared.global [%0], [%1], 16;"
                 :: "r"(dst), "l"(src));
}
__device__ __forceinline__ void cp_commit() {
    asm volatile("cp.async.commit_group;" ::: "memory");
}
template <int N>
__device__ __forceinline__ void cp_wait() {
    asm volatile("cp.async.wait_group %0;" :: "n"(N) : "memory");
}
__device__ __forceinline__ void mma16h(float* c, const uint32_t* a,
                                       uint32_t b0, uint32_t b1) {
    asm volatile(
        "mma.sync.aligned.m16n8k16.row.col.f32.f16.f16.f32 "
        "{%0,%1,%2,%3}, {%4,%5,%6,%7}, {%8,%9}, {%0,%1,%2,%3};"
        : "+f"(c[0]), "+f"(c[1]), "+f"(c[2]), "+f"(c[3])
        : "r"(a[0]), "r"(a[1]), "r"(a[2]), "r"(a[3]), "r"(b0), "r"(b1));
}
__device__ __forceinline__ void ldm4(uint32_t* r, uint32_t a) {
    asm volatile("ldmatrix.sync.aligned.m8n8.x4.shared.b16 {%0,%1,%2,%3}, [%4];"
                 : "=r"(r[0]), "=r"(r[1]), "=r"(r[2]), "=r"(r[3]) : "r"(a));
}
__device__ __forceinline__ void ldm4t(uint32_t* r, uint32_t a) {
    asm volatile("ldmatrix.sync.aligned.m8n8.x4.trans.shared.b16 {%0,%1,%2,%3}, [%4];"
                 : "=r"(r[0]), "=r"(r[1]), "=r"(r[2]), "=r"(r[3]) : "r"(a));
}
__device__ __forceinline__ uint32_t h2pack(float v0, float v1) {
    __half2 h = __floats2half2_rn(v0, v1);
    return *reinterpret_cast<uint32_t*>(&h);
}

// ---------------------------------------------------------------------------
// Conversion: x and the four W matrices -> fp16 copies (one float4/thread).
// ---------------------------------------------------------------------------
__global__ __launch_bounds__(256)
void round_conv(const float* __restrict__ x,  const float* __restrict__ Wq,
                const float* __restrict__ Wk, const float* __restrict__ Wv,
                const float* __restrict__ Wo)
{
    const int idx = blockIdx.x * 256 + threadIdx.x;
    const float4* src;
    uint32_t* dst;
    if (idx < 2097152) {                       // x: 8,388,608 floats
        src = (const float4*)x + idx;
        dst = (uint32_t*)g_xh + idx * 2;
    } else {
        const int wi  = idx - 2097152;
        const int z   = wi >> 18;              // 262,144 float4 per W
        const int off = wi & 262143;
        const float* w = (z == 0) ? Wq : (z == 1) ? Wk : (z == 2) ? Wv : Wo;
        src = (const float4*)w + off;
        dst = (uint32_t*)g_wh + ((size_t)z * 262144 + off) * 2;
    }
    const float4 v = *src;
    dst[0] = h2pack(v.x, v.y);
    dst[1] = h2pack(v.z, v.w);
}

// ---------------------------------------------------------------------------
// fp16 mma.sync GEMM (fp32 accumulate), ldmatrix feed, single-sync mainloop.
// CTA 128x128, K-chunk 64 (128 B fp16 rows), 3-stage cp.async, 256 threads.
// MODE 0: A=g_ath, W=g_wh[3], +bias, writes Cout fp32.
// MODE 1: A=g_xh, z selects g_wh[z]; epilogue writes fp16 g_qs/ks/vs.
// ---------------------------------------------------------------------------
static constexpr int GSTAGES   = 3;
static constexpr int NCHUNK    = 16;                  // 1024 / 64
static constexpr int STAGE_B   = 2 * 128 * 128;       // A 16KB + B 16KB
static constexpr int GEMM_SMEM = GSTAGES * STAGE_B;   // 98304 B

template <int MODE>
__global__ __launch_bounds__(256, 2)
void gemm_tc(const float* __restrict__ bias, float* __restrict__ Cout)
{
    extern __shared__ char smch[];
    const uint32_t sbase = smem_u32(smch);

    const int tid  = threadIdx.x;
    const int wid  = tid >> 5;
    const int lane = tid & 31;
    const int gID  = lane >> 2;
    const int ctg  = lane & 3;
    const int wRow = (wid & 1) * 64;
    const int wCol = (wid >> 1) * 32;

    const int brow = blockIdx.x;
    const int bcol = blockIdx.y;
    const int z    = (MODE == 0) ? 3 : blockIdx.z;

    const uint16_t* Ain = (MODE == 0) ? g_ath : g_xh;
    const char* ap = (const char*)(Ain + (size_t)(brow * 128) * DD);
    const char* wp = (const char*)(g_wh + (size_t)z * (DD * DD)
                                        + (size_t)(bcol * 128) * DD);

    // ldmatrix lane constants
    const int rA = lane & 15;          // A row-in-16
    const int sB = lane >> 4;          // granule-half selector (A) / row-group (B)
    const int rB = lane & 7;           // B row-within-8
    const int hB = (lane >> 3) & 1;    // B granule-half selector

    auto load_chunk = [&](int chunk, int stage) {
        const uint32_t aB = sbase + (uint32_t)(stage * STAGE_B);
        const uint32_t bB = aB + 16384u;
        const char* a0 = ap + chunk * 128;          // 64 fp16 cols = 128 B
        const char* w0 = wp + chunk * 128;
#pragma unroll
        for (int u = 0; u < 4; u++) {
            const int gi  = tid + 256 * u;          // 0..1023
            const int row = gi >> 3;
            const int ch  = gi & 7;
            const uint32_t off =
                (uint32_t)(row * 128 + ((ch ^ (row & 7)) << 4));
            cp16(aB + off, a0 + (size_t)row * 2048 + ch * 16);
            cp16(bB + off, w0 + (size_t)row * 2048 + ch * 16);
        }
        cp_commit();
    };

    float c[4][4][4];
#pragma unroll
    for (int i = 0; i < 4; i++)
#pragma unroll
        for (int j = 0; j < 4; j++)
#pragma unroll
            for (int r = 0; r < 4; r++) c[i][j][r] = 0.f;

    load_chunk(0, 0);
    load_chunk(1, 1);

    int stage = 0;
    for (int i = 0; i < NCHUNK; i++) {
        // wait for chunk i (pending: {i, i+1} or just {i} at the tail)
        if (i + 1 < NCHUNK) cp_wait<1>(); else cp_wait<0>();
        __syncthreads();   // chunk i visible to all; stage (i+2)%3 free
        if (i + 2 < NCHUNK) load_chunk(i + 2, (stage + 2) % GSTAGES);

        const uint32_t sA = sbase + (uint32_t)(stage * STAGE_B);
        const uint32_t sBa = sA + 16384u;
        uint32_t aBase[4], bBase[2];
#pragma unroll
        for (int mt = 0; mt < 4; mt++)
            aBase[mt] = sA + (uint32_t)((wRow + mt * 16 + rA) * 128);
#pragma unroll
        for (int ntp = 0; ntp < 2; ntp++)
            bBase[ntp] = sBa + (uint32_t)((wCol + ntp * 16 + sB * 8 + rB) * 128);

#pragma unroll
        for (int kb = 0; kb < 4; kb++) {            // 4 k16 blocks per chunk
            uint32_t a[4][4], b[2][4];
            const uint32_t offA = (uint32_t)(((2 * kb + sB) ^ (rA & 7)) << 4);
            const uint32_t offB = (uint32_t)(((2 * kb + hB) ^ rB) << 4);
#pragma unroll
            for (int mt = 0; mt < 4; mt++) ldm4(a[mt], aBase[mt] + offA);
#pragma unroll
            for (int ntp = 0; ntp < 2; ntp++) ldm4(b[ntp], bBase[ntp] + offB);
#pragma unroll
            for (int mt = 0; mt < 4; mt++)
#pragma unroll
                for (int ntp = 0; ntp < 2; ntp++) {
                    mma16h(c[mt][2 * ntp],     a[mt], b[ntp][0], b[ntp][1]);
                    mma16h(c[mt][2 * ntp + 1], a[mt], b[ntp][2], b[ntp][3]);
                }
        }
        stage = (stage + 1) % GSTAGES;
    }

#pragma unroll
    for (int mt = 0; mt < 4; mt++) {
#pragma unroll
        for (int half = 0; half < 2; half++) {
            const int m = brow * 128 + wRow + mt * 16 + gID + half * 8;
            if (MODE == 0) {
                float* rowp = &Cout[(size_t)m * DD + bcol * 128];
#pragma unroll
                for (int nt = 0; nt < 4; nt++) {
                    const int n = wCol + nt * 8 + ctg * 2;
                    float2 v;
                    v.x = c[mt][nt][half * 2 + 0] + bias[bcol * 128 + n];
                    v.y = c[mt][nt][half * 2 + 1] + bias[bcol * 128 + n + 1];
                    *reinterpret_cast<float2*>(&rowp[n]) = v;
                }
            } else {
                const int bb = m >> 11;
                const int s  = m & 2047;
                uint16_t* dst = (z == 0) ? g_qs : (z == 1) ? g_ks : g_vs;
                // q pre-scale folds 1/sqrt(64) AND log2(e) for exp2 softmax
                const float qs = (z == 0) ? 0.125f * 1.44269504088896f : 1.0f;
#pragma unroll
                for (int nt = 0; nt < 4; nt++) {
                    const int n  = bcol * 128 + wCol + nt * 8 + ctg * 2;
                    const int h  = n >> 6;
                    const int hs = n & 63;
                    const uint32_t hv = h2pack(c[mt][nt][half * 2 + 0] * qs,
                                               c[mt][nt][half * 2 + 1] * qs);
                    *(uint32_t*)&dst[((size_t)(bb * HH + h) * SS + s) * 64 + hs] = hv;
                }
            }
        }
    }
}

// ---------------------------------------------------------------------------
// Causal flash attention, single-pass fp16, half2 exp2 softmax.
// 128 queries/CTA, 64-key tiles, 2-stage cp.async (R11 loop structure).
// smem: K[2][8K] | V[2][8K] | Qstage[8][2K] = 48 KB.
// ---------------------------------------------------------------------------
static constexpr int ATTN_SMEM = 49152;

__global__ __launch_bounds__(256)
void attn_tc()
{
    extern __shared__ char smem[];
    const uint32_t sbase = smem_u32(smem);

    const int tid  = threadIdx.x;
    const int w    = tid >> 5;
    const int lane = tid & 31;
    const int gID  = lane >> 2;
    const int ctg  = lane & 3;

    const int qt = (int)gridDim.x - 1 - (int)blockIdx.x;  // heavy tiles first
    const int bh = blockIdx.y;
    const int q0 = qt * 128;
    const int NT = 2 * qt + 2;

    const char* kgB = (const char*)g_ks + (size_t)bh * SS * 128;
    const char* vgB = (const char*)g_vs + (size_t)bh * SS * 128;
    const char* qgB = (const char*)g_qs + (size_t)(bh * SS + q0 + w * 16) * 128;

    const uint32_t PsB = sbase + 32768u + (uint32_t)w * 2048u;

    const int rB = lane & 7;
    const int hB = (lane >> 3) & 1;
    const int sB = lane >> 4;
    const int rA = lane & 15;

    auto loadKV = [&](int t, int st) {
        const uint32_t kb = sbase + (uint32_t)st * 8192u;
        const uint32_t vb = sbase + 16384u + (uint32_t)st * 8192u;
        const char* kp = kgB + (size_t)t * 64 * 128;
        const char* vp = vgB + (size_t)t * 64 * 128;
#pragma unroll
        for (int u = 0; u < 2; u++) {
            const int gi = tid + 256 * u;
            const int row = gi >> 3, ch = gi & 7;
            const uint32_t off = (uint32_t)(row * 128 + ((ch ^ (row & 7)) << 4));
            cp16(kb + off, kp + row * 128 + ch * 16);
            cp16(vb + off, vp + row * 128 + ch * 16);
        }
        cp_commit();
    };

    loadKV(0, 0);
    // stage Q through this warp's private region (read once into registers)
#pragma unroll
    for (int u = 0; u < 4; u++) {
        const int idx = lane + 32 * u;
        const int row = idx >> 3, ch = idx & 7;
        const uint32_t off = (uint32_t)(row * 128 + ((ch ^ (row & 7)) << 4));
        cp16(PsB + off, qgB + row * 128 + ch * 16);
    }
    cp_commit();
    cp_wait<0>();
    __syncwarp();

    uint32_t qf[4][4];
#pragma unroll
    for (int j = 0; j < 4; j++)
        ldm4(qf[j], PsB + (uint32_t)(rA * 128 + (((2 * j + sB) ^ (rA & 7)) << 4)));
    __syncthreads();

    float o[8][4];
#pragma unroll
    for (int nt = 0; nt < 8; nt++)
#pragma unroll
        for (int i = 0; i < 4; i++) o[nt][i] = 0.f;
    float m_[2] = {-1e30f, -1e30f};
    float l_[2] = {0.f, 0.f};

    for (int t = 0; t < NT; t++) {
        if (t) __syncthreads();
        if (t + 1 < NT) { loadKV(t + 1, (t + 1) & 1); cp_wait<1>(); }
        else            { cp_wait<0>(); }
        __syncthreads();

        if (t * 64 <= q0 + w * 16 + 15) {
            const uint32_t kst = sbase + (uint32_t)(t & 1) * 8192u;
            const uint32_t vst = sbase + 16384u + (uint32_t)(t & 1) * 8192u;

            int ntpLim = 4;
            if (t >= 2 * qt)
                ntpLim = min(4, (q0 + 16 * w + 15 - t * 64) / 16 + 1);

            float s[8][4];
#pragma unroll
            for (int nt = 0; nt < 8; nt++)
#pragma unroll
                for (int i = 0; i < 4; i++) s[nt][i] = 0.f;

#pragma unroll
            for (int ntp = 0; ntp < 4; ntp++) {
                if (ntp >= ntpLim) continue;
                const uint32_t ntb = kst + (uint32_t)((2 * ntp + sB) * 1024 + rB * 128);
#pragma unroll
                for (int j = 0; j < 4; j++) {
                    uint32_t kf[4];
                    ldm4(kf, ntb + (uint32_t)(((2 * j + hB) ^ rB) << 4));
                    mma16h(s[2 * ntp],     qf[j], kf[0], kf[1]);
                    mma16h(s[2 * ntp + 1], qf[j], kf[2], kf[3]);
                }
            }

            if (t >= 2 * qt) {
#pragma unroll
                for (int nt = 0; nt < 8; nt++)
#pragma unroll
                    for (int i = 0; i < 4; i++) {
                        const int kg = t * 64 + nt * 8 + 2 * ctg + (i & 1);
                        const int qg = q0 + w * 16 + gID + (i >> 1) * 8;
                        if (kg > qg) s[nt][i] = -1e30f;
                    }
            }

            // online softmax in log2 domain; exp via half2 MUFU, and the
            // half2 results ARE the PV A-fragment registers (no repack).
            uint32_t ph[8][2];
#pragma unroll
            for (int h2 = 0; h2 < 2; h2++) {
                float rm = -1e30f;
#pragma unroll
                for (int nt = 0; nt < 8; nt++)
                    rm = fmaxf(rm, fmaxf(s[nt][2 * h2], s[nt][2 * h2 + 1]));
                rm = fmaxf(rm, __shfl_xor_sync(0xffffffffu, rm, 1));
                rm = fmaxf(rm, __shfl_xor_sync(0xffffffffu, rm, 2));
                const float mn    = fmaxf(m_[h2], rm);
                const float alpha = exp2f(m_[h2] - mn);
                m_[h2] = mn;
                float rs = 0.f;
#pragma unroll
                for (int nt = 0; nt < 8; nt++) {
                    const __half2 hp = h2exp2(
                        __floats2half2_rn(s[nt][2 * h2]     - mn,
                                          s[nt][2 * h2 + 1] - mn));
                    ph[nt][h2] = *(const uint32_t*)&hp;
                    const float2 pf32 = __half22float2(hp);
                    rs += pf32.x + pf32.y;
                }
                rs += __shfl_xor_sync(0xffffffffu, rs, 1);
                rs += __shfl_xor_sync(0xffffffffu, rs, 2);
                l_[h2] = l_[h2] * alpha + rs;
#pragma unroll
                for (int nt = 0; nt < 8; nt++) {
                    o[nt][2 * h2]     *= alpha;
                    o[nt][2 * h2 + 1] *= alpha;
                }
            }

            // O += P V (P already fp16 in ph; V via ldmatrix.trans)
#pragma unroll
            for (int j = 0; j < 4; j++) {
                if (j >= ntpLim) continue;
                uint32_t pf[4];
                pf[0] = ph[2 * j][0];
                pf[1] = ph[2 * j][1];
                pf[2] = ph[2 * j + 1][0];
                pf[3] = ph[2 * j + 1][1];
                const uint32_t jrow = vst + (uint32_t)((2 * j + hB) * 1024 + rB * 128);
#pragma unroll
                for (int ntp = 0; ntp < 4; ntp++) {
                    uint32_t vf[4];
                    ldm4t(vf, jrow + (uint32_t)(((2 * ntp + sB) ^ rB) << 4));
                    mma16h(o[2 * ntp],     pf, vf[0], vf[1]);
                    mma16h(o[2 * ntp + 1], pf, vf[2], vf[3]);
                }
            }
        }
    }

    // normalize, write fp16 [b, s, h*64+d] for the fp16 output GEMM
    const int hh = bh & 15;
    const int bb = bh >> 4;
    const float i0 = 1.f / l_[0];
    const float i1 = 1.f / l_[1];
    const int qg0 = q0 + w * 16 + gID;
#pragma unroll
    for (int nt = 0; nt < 8; nt++) {
        const int d0 = hh * 64 + nt * 8 + 2 * ctg;
        *(uint32_t*)&g_ath[(size_t)(bb * SS + qg0) * DD + d0] =
            h2pack(o[nt][0] * i0, o[nt][1] * i0);
        *(uint32_t*)&g_ath[(size_t)(bb * SS + qg0 + 8) * DD + d0] =
            h2pack(o[nt][2] * i1, o[nt][3] * i1);
    }
}

// ---------------------------------------------------------------------------

extern "C" void kernel_launch(void* const* d_in, const int* in_sizes, int n_in,
                              void* d_out, int out_size)
{
    const float* x  = (const float*)d_in[0];
    const float* Wk = (const float*)d_in[1];
    const float* Wq = (const float*)d_in[2];
    const float* Wv = (const float*)d_in[3];
    const float* Wo = (const float*)d_in[4];
    const float* bo = (const float*)d_in[5];
    float* out = (float*)d_out;

    cudaFuncSetAttribute(attn_tc,
                         cudaFuncAttributeMaxDynamicSharedMemorySize, ATTN_SMEM);
    cudaFuncSetAttribute(gemm_tc<0>,
                         cudaFuncAttributeMaxDynamicSharedMemorySize, GEMM_SMEM);
    cudaFuncSetAttribute(gemm_tc<1>,
                         cudaFuncAttributeMaxDynamicSharedMemorySize, GEMM_SMEM);

    // 0) fp16-convert x and weights (g_wh order: Wq, Wk, Wv, Wo)
    round_conv<<<12288, 256>>>(x, Wq, Wk, Wv, Wo);

    // 1) QKV projections (fp16 MMA, fp32 accum) -> fp16 q/k/v
    gemm_tc<1><<<dim3(BB * SS / 128, DD / 128, 3), 256, GEMM_SMEM>>>(
        nullptr, nullptr);

    // 2) Tensor-core causal flash attention (fp16, h2exp2 softmax) -> g_ath
    attn_tc<<<dim3(SS / 128, BB * HH), 256, ATTN_SMEM>>>();

    // 3) Output projection (fp16 MMA): out = g_ath @ Wo^T + bo
    gemm_tc<0><<<dim3(BB * SS / 128, DD / 128, 1), 256, GEMM_SMEM>>>(bo, out);
}

// round 14
// speedup vs baseline: 1.0300x; 1.0037x over previous
#include <cuda_runtime.h>
#include <cuda_fp16.h>
#include <cstdint>

static constexpr int BB  = 4;
static constexpr int SS  = 2048;
static constexpr int DD  = 1024;
static constexpr int HH  = 16;
static constexpr int HSZ = 64;

// Scratch. Everything fp16 (same 11-bit mantissa grid as tf32; fp32 accum).
// q/k/v: [b*h][row][64] fp16 = 128 B rows. q pre-scaled by 0.125*log2(e).
__device__ uint16_t g_qs[BB * HH * SS * 64];
__device__ uint16_t g_ks[BB * HH * SS * 64];
__device__ uint16_t g_vs[BB * HH * SS * 64];
__device__ uint16_t g_ath[BB * SS * DD];     // attention out, fp16
__device__ uint16_t g_xh[BB * SS * DD];      // x, fp16
__device__ uint16_t g_wh[4 * DD * DD];       // Wq|Wk|Wv|Wo, fp16

// ---------------------------------------------------------------------------
// Helpers (sm_80-era PTX only: valid on plain compute_103)
// ---------------------------------------------------------------------------
__device__ __forceinline__ uint32_t smem_u32(const void* p) {
    uint32_t a;
    asm("{ .reg .u64 t; cvta.to.shared.u64 t, %1; cvt.u32.u64 %0, t; }"
        : "=r"(a) : "l"(p));
    return a;
}
__device__ __forceinline__ void cp16(uint32_t dst, const void* src) {
    asm volatile("cp.async.cg.shared.global [%0], [%1], 16;"
                 :: "r"(dst), "l"(src));
}
__device__ __forceinline__ void cp_commit() {
    asm volatile("cp.async.commit_group;" ::: "memory");
}
template <int N>
__device__ __forceinline__ void cp_wait() {
    asm volatile("cp.async.wait_group %0;" :: "n"(N) : "memory");
}
__device__ __forceinline__ void mma16h(float* c, const uint32_t* a,
                                       uint32_t b0, uint32_t b1) {
    asm volatile(
        "mma.sync.aligned.m16n8k16.row.col.f32.f16.f16.f32 "
        "{%0,%1,%2,%3}, {%4,%5,%6,%7}, {%8,%9}, {%0,%1,%2,%3};"
        : "+f"(c[0]), "+f"(c[1]), "+f"(c[2]), "+f"(c[3])
        : "r"(a[0]), "r"(a[1]), "r"(a[2]), "r"(a[3]), "r"(b0), "r"(b1));
}
__device__ __forceinline__ void ldm4(uint32_t* r, uint32_t a) {
    asm volatile("ldmatrix.sync.aligned.m8n8.x4.shared.b16 {%0,%1,%2,%3}, [%4];"
                 : "=r"(r[0]), "=r"(r[1]), "=r"(r[2]), "=r"(r[3]) : "r"(a));
}
__device__ __forceinline__ void ldm4t(uint32_t* r, uint32_t a) {
    asm volatile("ldmatrix.sync.aligned.m8n8.x4.trans.shared.b16 {%0,%1,%2,%3}, [%4];"
                 : "=r"(r[0]), "=r"(r[1]), "=r"(r[2]), "=r"(r[3]) : "r"(a));
}
__device__ __forceinline__ uint32_t h2pack(float v0, float v1) {
    __half2 h = __floats2half2_rn(v0, v1);
    return *reinterpret_cast<uint32_t*>(&h);
}

// ---------------------------------------------------------------------------
// Conversion: x and the four W matrices -> fp16 copies (one float4/thread).
// ---------------------------------------------------------------------------
__global__ __launch_bounds__(256)
void round_conv(const float* __restrict__ x,  const float* __restrict__ Wq,
                const float* __restrict__ Wk, const float* __restrict__ Wv,
                const float* __restrict__ Wo)
{
    const int idx = blockIdx.x * 256 + threadIdx.x;
    const float4* src;
    uint32_t* dst;
    if (idx < 2097152) {                       // x: 8,388,608 floats
        src = (const float4*)x + idx;
        dst = (uint32_t*)g_xh + idx * 2;
    } else {
        const int wi  = idx - 2097152;
        const int z   = wi >> 18;              // 262,144 float4 per W
        const int off = wi & 262143;
        const float* w = (z == 0) ? Wq : (z == 1) ? Wk : (z == 2) ? Wv : Wo;
        src = (const float4*)w + off;
        dst = (uint32_t*)g_wh + ((size_t)z * 262144 + off) * 2;
    }
    const float4 v = *src;
    dst[0] = h2pack(v.x, v.y);
    dst[1] = h2pack(v.z, v.w);
}

// ---------------------------------------------------------------------------
// fp16 mma.sync GEMM (fp32 accumulate). CTA 128x128, 4 warps in a 2x2 grid,
// 64x64 warp tile: fragment smem traffic = (2+2)*16KB per chunk (was 96KB
// with the 2x4 grid) -> smem feed and HMMA balance. 3-stage cp.async.
// MODE 0: A=g_ath, W=g_wh[3], +bias, writes Cout fp32.
// MODE 1: A=g_xh, z selects g_wh[z]; epilogue writes fp16 g_qs/ks/vs.
// ---------------------------------------------------------------------------
static constexpr int GSTAGES   = 3;
static constexpr int NCHUNK    = 16;                  // 1024 / 64
static constexpr int STAGE_B   = 2 * 128 * 128;       // A 16KB + B 16KB
static constexpr int GEMM_SMEM = GSTAGES * STAGE_B;   // 98304 B

template <int MODE>
__global__ __launch_bounds__(128, 2)
void gemm_tc(const float* __restrict__ bias, float* __restrict__ Cout)
{
    extern __shared__ char smch[];
    const uint32_t sbase = smem_u32(smch);

    const int tid  = threadIdx.x;
    const int wid  = tid >> 5;          // 0..3
    const int lane = tid & 31;
    const int gID  = lane >> 2;
    const int ctg  = lane & 3;
    const int wRow = (wid & 1) * 64;    // 2x2 warp grid
    const int wCol = (wid >> 1) * 64;

    const int brow = blockIdx.x;
    const int bcol = blockIdx.y;
    const int z    = (MODE == 0) ? 3 : blockIdx.z;

    const uint16_t* Ain = (MODE == 0) ? g_ath : g_xh;
    const char* ap = (const char*)(Ain + (size_t)(brow * 128) * DD);
    const char* wp = (const char*)(g_wh + (size_t)z * (DD * DD)
                                        + (size_t)(bcol * 128) * DD);

    // ldmatrix lane constants
    const int rA = lane & 15;          // A row-in-16
    const int sB = lane >> 4;          // granule-half selector (A) / row-group (B)
    const int rB = lane & 7;           // B row-within-8
    const int hB = (lane >> 3) & 1;    // B granule-half selector

    auto load_chunk = [&](int chunk, int stage) {
        const uint32_t aB = sbase + (uint32_t)(stage * STAGE_B);
        const uint32_t bB = aB + 16384u;
        const char* a0 = ap + chunk * 128;          // 64 fp16 cols = 128 B
        const char* w0 = wp + chunk * 128;
#pragma unroll
        for (int u = 0; u < 8; u++) {
            const int gi  = tid + 128 * u;          // 0..1023
            const int row = gi >> 3;
            const int ch  = gi & 7;
            const uint32_t off =
                (uint32_t)(row * 128 + ((ch ^ (row & 7)) << 4));
            cp16(aB + off, a0 + (size_t)row * 2048 + ch * 16);
            cp16(bB + off, w0 + (size_t)row * 2048 + ch * 16);
        }
        cp_commit();
    };

    float c[4][8][4];
#pragma unroll
    for (int i = 0; i < 4; i++)
#pragma unroll
        for (int j = 0; j < 8; j++)
#pragma unroll
            for (int r = 0; r < 4; r++) c[i][j][r] = 0.f;

    load_chunk(0, 0);
    load_chunk(1, 1);

    int stage = 0;
    for (int i = 0; i < NCHUNK; i++) {
        // wait for chunk i (pending: {i, i+1} or just {i} at the tail)
        if (i + 1 < NCHUNK) cp_wait<1>(); else cp_wait<0>();
        __syncthreads();   // chunk i visible to all; stage (i+2)%3 free
        if (i + 2 < NCHUNK) load_chunk(i + 2, (stage + 2) % GSTAGES);

        const uint32_t sA = sbase + (uint32_t)(stage * STAGE_B);
        const uint32_t sBa = sA + 16384u;
        uint32_t aBase[4], bBase[4];
#pragma unroll
        for (int mt = 0; mt < 4; mt++)
            aBase[mt] = sA + (uint32_t)((wRow + mt * 16 + rA) * 128);
#pragma unroll
        for (int ntp = 0; ntp < 4; ntp++)
            bBase[ntp] = sBa + (uint32_t)((wCol + ntp * 16 + sB * 8 + rB) * 128);

#pragma unroll
        for (int kb = 0; kb < 4; kb++) {            // 4 k16 blocks per chunk
            uint32_t a[4][4], b[4][4];
            const uint32_t offA = (uint32_t)(((2 * kb + sB) ^ (rA & 7)) << 4);
            const uint32_t offB = (uint32_t)(((2 * kb + hB) ^ rB) << 4);
#pragma unroll
            for (int mt = 0; mt < 4; mt++) ldm4(a[mt], aBase[mt] + offA);
#pragma unroll
            for (int ntp = 0; ntp < 4; ntp++) ldm4(b[ntp], bBase[ntp] + offB);
#pragma unroll
            for (int mt = 0; mt < 4; mt++)
#pragma unroll
                for (int ntp = 0; ntp < 4; ntp++) {
                    mma16h(c[mt][2 * ntp],     a[mt], b[ntp][0], b[ntp][1]);
                    mma16h(c[mt][2 * ntp + 1], a[mt], b[ntp][2], b[ntp][3]);
                }
        }
        stage = (stage + 1) % GSTAGES;
    }

#pragma unroll
    for (int mt = 0; mt < 4; mt++) {
#pragma unroll
        for (int half = 0; half < 2; half++) {
            const int m = brow * 128 + wRow + mt * 16 + gID + half * 8;
            if (MODE == 0) {
                float* rowp = &Cout[(size_t)m * DD + bcol * 128];
#pragma unroll
                for (int nt = 0; nt < 8; nt++) {
                    const int n = wCol + nt * 8 + ctg * 2;
                    float2 v;
                    v.x = c[mt][nt][half * 2 + 0] + bias[bcol * 128 + n];
                    v.y = c[mt][nt][half * 2 + 1] + bias[bcol * 128 + n + 1];
                    *reinterpret_cast<float2*>(&rowp[n]) = v;
                }
            } else {
                const int bb = m >> 11;
                const int s  = m & 2047;
                uint16_t* dst = (z == 0) ? g_qs : (z == 1) ? g_ks : g_vs;
                // q pre-scale folds 1/sqrt(64) AND log2(e) for exp2 softmax
                const float qs = (z == 0) ? 0.125f * 1.44269504088896f : 1.0f;
#pragma unroll
                for (int nt = 0; nt < 8; nt++) {
                    const int n  = bcol * 128 + wCol + nt * 8 + ctg * 2;
                    const int h  = n >> 6;
                    const int hs = n & 63;
                    const uint32_t hv = h2pack(c[mt][nt][half * 2 + 0] * qs,
                                               c[mt][nt][half * 2 + 1] * qs);
                    *(uint32_t*)&dst[((size_t)(bb * HH + h) * SS + s) * 64 + hs] = hv;
                }
            }
        }
    }
}

// ---------------------------------------------------------------------------
// Causal flash attention, single-pass fp16, half2 exp2 softmax (R13, best).
// 128 queries/CTA, 64-key tiles, 2-stage cp.async.
// smem: K[2][8K] | V[2][8K] | Qstage[8][2K] = 48 KB.
// ---------------------------------------------------------------------------
static constexpr int ATTN_SMEM = 49152;

__global__ __launch_bounds__(256)
void attn_tc()
{
    extern __shared__ char smem[];
    const uint32_t sbase = smem_u32(smem);

    const int tid  = threadIdx.x;
    const int w    = tid >> 5;
    const int lane = tid & 31;
    const int gID  = lane >> 2;
    const int ctg  = lane & 3;

    const int qt = (int)gridDim.x - 1 - (int)blockIdx.x;  // heavy tiles first
    const int bh = blockIdx.y;
    const int q0 = qt * 128;
    const int NT = 2 * qt + 2;

    const char* kgB = (const char*)g_ks + (size_t)bh * SS * 128;
    const char* vgB = (const char*)g_vs + (size_t)bh * SS * 128;
    const char* qgB = (const char*)g_qs + (size_t)(bh * SS + q0 + w * 16) * 128;

    const uint32_t PsB = sbase + 32768u + (uint32_t)w * 2048u;

    const int rB = lane & 7;
    const int hB = (lane >> 3) & 1;
    const int sB = lane >> 4;
    const int rA = lane & 15;

    auto loadKV = [&](int t, int st) {
        const uint32_t kb = sbase + (uint32_t)st * 8192u;
        const uint32_t vb = sbase + 16384u + (uint32_t)st * 8192u;
        const char* kp = kgB + (size_t)t * 64 * 128;
        const char* vp = vgB + (size_t)t * 64 * 128;
#pragma unroll
        for (int u = 0; u < 2; u++) {
            const int gi = tid + 256 * u;
            const int row = gi >> 3, ch = gi & 7;
            const uint32_t off = (uint32_t)(row * 128 + ((ch ^ (row & 7)) << 4));
            cp16(kb + off, kp + row * 128 + ch * 16);
            cp16(vb + off, vp + row * 128 + ch * 16);
        }
        cp_commit();
    };

    loadKV(0, 0);
    // stage Q through this warp's private region (read once into registers)
#pragma unroll
    for (int u = 0; u < 4; u++) {
        const int idx = lane + 32 * u;
        const int row = idx >> 3, ch = idx & 7;
        const uint32_t off = (uint32_t)(row * 128 + ((ch ^ (row & 7)) << 4));
        cp16(PsB + off, qgB + row * 128 + ch * 16);
    }
    cp_commit();
    cp_wait<0>();
    __syncwarp();

    uint32_t qf[4][4];
#pragma unroll
    for (int j = 0; j < 4; j++)
        ldm4(qf[j], PsB + (uint32_t)(rA * 128 + (((2 * j + sB) ^ (rA & 7)) << 4)));
    __syncthreads();

    float o[8][4];
#pragma unroll
    for (int nt = 0; nt < 8; nt++)
#pragma unroll
        for (int i = 0; i < 4; i++) o[nt][i] = 0.f;
    float m_[2] = {-1e30f, -1e30f};
    float l_[2] = {0.f, 0.f};

    for (int t = 0; t < NT; t++) {
        if (t) __syncthreads();
        if (t + 1 < NT) { loadKV(t + 1, (t + 1) & 1); cp_wait<1>(); }
        else            { cp_wait<0>(); }
        __syncthreads();

        if (t * 64 <= q0 + w * 16 + 15) {
            const uint32_t kst = sbase + (uint32_t)(t & 1) * 8192u;
            const uint32_t vst = sbase + 16384u + (uint32_t)(t & 1) * 8192u;

            int ntpLim = 4;
            if (t >= 2 * qt)
                ntpLim = min(4, (q0 + 16 * w + 15 - t * 64) / 16 + 1);

            float s[8][4];
#pragma unroll
            for (int nt = 0; nt < 8; nt++)
#pragma unroll
                for (int i = 0; i < 4; i++) s[nt][i] = 0.f;

#pragma unroll
            for (int ntp = 0; ntp < 4; ntp++) {
                if (ntp >= ntpLim) continue;
                const uint32_t ntb = kst + (uint32_t)((2 * ntp + sB) * 1024 + rB * 128);
#pragma unroll
                for (int j = 0; j < 4; j++) {
                    uint32_t kf[4];
                    ldm4(kf, ntb + (uint32_t)(((2 * j + hB) ^ rB) << 4));
                    mma16h(s[2 * ntp],     qf[j], kf[0], kf[1]);
                    mma16h(s[2 * ntp + 1], qf[j], kf[2], kf[3]);
                }
            }

            if (t >= 2 * qt) {
#pragma unroll
                for (int nt = 0; nt < 8; nt++)
#pragma unroll
                    for (int i = 0; i < 4; i++) {
                        const int kg = t * 64 + nt * 8 + 2 * ctg + (i & 1);
                        const int qg = q0 + w * 16 + gID + (i >> 1) * 8;
                        if (kg > qg) s[nt][i] = -1e30f;
                    }
            }

            // online softmax in log2 domain; exp via half2 MUFU, and the
            // half2 results ARE the PV A-fragment registers (no repack).
            uint32_t ph[8][2];
#pragma unroll
            for (int h2 = 0; h2 < 2; h2++) {
                float rm = -1e30f;
#pragma unroll
                for (int nt = 0; nt < 8; nt++)
                    rm = fmaxf(rm, fmaxf(s[nt][2 * h2], s[nt][2 * h2 + 1]));
                rm = fmaxf(rm, __shfl_xor_sync(0xffffffffu, rm, 1));
                rm = fmaxf(rm, __shfl_xor_sync(0xffffffffu, rm, 2));
                const float mn    = fmaxf(m_[h2], rm);
                const float alpha = exp2f(m_[h2] - mn);
                m_[h2] = mn;
                float rs = 0.f;
#pragma unroll
                for (int nt = 0; nt < 8; nt++) {
                    const __half2 hp = h2exp2(
                        __floats2half2_rn(s[nt][2 * h2]     - mn,
                                          s[nt][2 * h2 + 1] - mn));
                    ph[nt][h2] = *(const uint32_t*)&hp;
                    const float2 pf32 = __half22float2(hp);
                    rs += pf32.x + pf32.y;
                }
                rs += __shfl_xor_sync(0xffffffffu, rs, 1);
                rs += __shfl_xor_sync(0xffffffffu, rs, 2);
                l_[h2] = l_[h2] * alpha + rs;
#pragma unroll
                for (int nt = 0; nt < 8; nt++) {
                    o[nt][2 * h2]     *= alpha;
                    o[nt][2 * h2 + 1] *= alpha;
                }
            }

            // O += P V (P already fp16 in ph; V via ldmatrix.trans)
#pragma unroll
            for (int j = 0; j < 4; j++) {
                if (j >= ntpLim) continue;
                uint32_t pf[4];
                pf[0] = ph[2 * j][0];
                pf[1] = ph[2 * j][1];
                pf[2] = ph[2 * j + 1][0];
                pf[3] = ph[2 * j + 1][1];
                const uint32_t jrow = vst + (uint32_t)((2 * j + hB) * 1024 + rB * 128);
#pragma unroll
                for (int ntp = 0; ntp < 4; ntp++) {
                    uint32_t vf[4];
                    ldm4t(vf, jrow + (uint32_t)(((2 * ntp + sB) ^ rB) << 4));
                    mma16h(o[2 * ntp],     pf, vf[0], vf[1]);
                    mma16h(o[2 * ntp + 1], pf, vf[2], vf[3]);
                }
            }
        }
    }

    // normalize, write fp16 [b, s, h*64+d] for the fp16 output GEMM
    const int hh = bh & 15;
    const int bb = bh >> 4;
    const float i0 = 1.f / l_[0];
    const float i1 = 1.f / l_[1];
    const int qg0 = q0 + w * 16 + gID;
#pragma unroll
    for (int nt = 0; nt < 8; nt++) {
        const int d0 = hh * 64 + nt * 8 + 2 * ctg;
        *(uint32_t*)&g_ath[(size_t)(bb * SS + qg0) * DD + d0] =
            h2pack(o[nt][0] * i0, o[nt][1] * i0);
        *(uint32_t*)&g_ath[(size_t)(bb * SS + qg0 + 8) * DD + d0] =
            h2pack(o[nt][2] * i1, o[nt][3] * i1);
    }
}

// ---------------------------------------------------------------------------

extern "C" void kernel_launch(void* const* d_in, const int* in_sizes, int n_in,
                              void* d_out, int out_size)
{
    const float* x  = (const float*)d_in[0];
    const float* Wk = (const float*)d_in[1];
    const float* Wq = (const float*)d_in[2];
    const float* Wv = (const float*)d_in[3];
    const float* Wo = (const float*)d_in[4];
    const float* bo = (const float*)d_in[5];
    float* out = (float*)d_out;

    cudaFuncSetAttribute(attn_tc,
                         cudaFuncAttributeMaxDynamicSharedMemorySize, ATTN_SMEM);
    cudaFuncSetAttribute(gemm_tc<0>,
                         cudaFuncAttributeMaxDynamicSharedMemorySize, GEMM_SMEM);
    cudaFuncSetAttribute(gemm_tc<1>,
                         cudaFuncAttributeMaxDynamicSharedMemorySize, GEMM_SMEM);

    // 0) fp16-convert x and weights (g_wh order: Wq, Wk, Wv, Wo)
    round_conv<<<12288, 256>>>(x, Wq, Wk, Wv, Wo);

    // 1) QKV projections (fp16 MMA, fp32 accum, 64x64 warp tiles)
    gemm_tc<1><<<dim3(BB * SS / 128, DD / 128, 3), 128, GEMM_SMEM>>>(
        nullptr, nullptr);

    // 2) Tensor-core causal flash attention (fp16, h2exp2 softmax) -> g_ath
    attn_tc<<<dim3(SS / 128, BB * HH), 256, ATTN_SMEM>>>();

    // 3) Output projection (fp16 MMA): out = g_ath @ Wo^T + bo
    gemm_tc<0><<<dim3(BB * SS / 128, DD / 128, 1), 128, GEMM_SMEM>>>(bo, out);
}